// round 15
// baseline (speedup 1.0000x reference)
#include <cuda_runtime.h>
#include <cuda_fp16.h>
#include <cstdint>

// Problem constants
#define E_TOTAL   640000
#define N_NODES   20000
#define N_GRAPHS  16
#define TILE_M    128
#define NTHREADS  512

#define LDA  68   // X buf / H rows [128][64 h2], padded (h2 units)

// smem byte offsets: two X buffers; H aliases buf0
#define SMEM_X0   0        // 128*68*4 = 34816
#define SMEM_X1   34816    // -> 69632
#define SMEM_H    0
#define OFF_S     69632
#define OFF_R     70144
#define OFF_G     70656
#define OFF_MSK   71168
#define OFF_B1    71680
#define OFF_B2    72192
#define SMEM_BYTES 72448

// ---------- scratch ----------
__device__ __half2 g_mn2[N_NODES * 32];    // masked nodes [node][32 h2]
__device__ __half2 g_ga2[N_GRAPHS * 32];   // global_attr fp16 [g][32 h2]
// fragment-linear weights: [s][n8][lane][2] h2 (one uint2 per lane)
__device__ __half2 g_w1f[16 * 16 * 32 * 2];   // 64KB
__device__ __half2 g_w2f[8 * 8 * 32 * 2];     // 16KB
__device__ int     g_is64;

__device__ __forceinline__ void mma_f16(float c[4], const uint32_t a[4], const uint32_t b[2]) {
    asm volatile(
        "mma.sync.aligned.m16n8k16.row.col.f32.f16.f16.f32 "
        "{%0,%1,%2,%3}, {%4,%5,%6,%7}, {%8,%9}, {%0,%1,%2,%3};"
        : "+f"(c[0]), "+f"(c[1]), "+f"(c[2]), "+f"(c[3])
        : "r"(a[0]), "r"(a[1]), "r"(a[2]), "r"(a[3]), "r"(b[0]), "r"(b[1]));
}
__device__ __forceinline__ uint32_t h2u(__half2 h) { return *(uint32_t*)&h; }

// Streaming loads: do NOT allocate in L1D (reserve L1D for weight-frag tables)
__device__ __forceinline__ uint2 ldg_na_u2(const void* p) {
    uint2 u;
    asm volatile("ld.global.L1::no_allocate.v2.u32 {%0,%1}, [%2];"
                 : "=r"(u.x), "=r"(u.y) : "l"(p));
    return u;
}
__device__ __forceinline__ float4 ldg_na_f4(const void* p) {
    float4 v;
    asm volatile("ld.global.L1::no_allocate.v4.f32 {%0,%1,%2,%3}, [%4];"
                 : "=f"(v.x), "=f"(v.y), "=f"(v.z), "=f"(v.w) : "l"(p));
    return v;
}

// ---------- single prep kernel ----------
// blocks [0,2500): masked nodes; [2500,2564): W1 frag-linear; [2564,2580): W2
// frag-linear; [2580,2582): global_attr fp16; 2582: index dtype detect.
#define PREP_BLOCKS 2583
__global__ void prep_all(const float* __restrict__ na, const float* __restrict__ nm,
                         const float* __restrict__ W1, const float* __restrict__ W2,
                         const float* __restrict__ ga, const int* __restrict__ ei_words) {
    int bid = blockIdx.x, tid = threadIdx.x;
    if (bid < 2500) {
        int i = bid * 256 + tid;
        if (i < N_NODES * 32) {
            int node = i >> 5, c2 = i & 31;
            float m = nm[node];
            const float* s = na + (size_t)node * 64 + c2 * 2;
            g_mn2[i] = __floats2half2_rn(s[0] * m, s[1] * m);
        }
    } else if (bid < 2564) {
        // W1 [256][128] -> frag-linear: j = ((s*16+n8)*32+lane)*2+reg
        int j = (bid - 2500) * 256 + tid;       // < 16384
        int s   = j >> 10;
        int rem = j & 1023;
        int n8  = rem >> 6;
        int lane = (rem >> 1) & 31;
        int reg  = rem & 1;
        int g = lane >> 2, t = lane & 3;
        int n  = n8 * 8 + g;
        int k2 = s * 8 + t + reg * 4;
        g_w1f[j] = __floats2half2_rn(W1[(2 * k2) * 128 + n], W1[(2 * k2 + 1) * 128 + n]);
    } else if (bid < 2580) {
        // W2 [128][64] -> frag-linear
        int j = (bid - 2564) * 256 + tid;       // < 4096
        int s   = j >> 9;
        int rem = j & 511;
        int n8  = rem >> 6;
        int lane = (rem >> 1) & 31;
        int reg  = rem & 1;
        int g = lane >> 2, t = lane & 3;
        int n  = n8 * 8 + g;
        int k2 = s * 8 + t + reg * 4;
        g_w2f[j] = __floats2half2_rn(W2[(2 * k2) * 64 + n], W2[(2 * k2 + 1) * 64 + n]);
    } else if (bid < 2582) {
        int j = (bid - 2580) * 256 + tid;       // < 512
        if (j < N_GRAPHS * 32) {
            int gi = j >> 5, c2 = j & 31;
            g_ga2[j] = __floats2half2_rn(ga[gi * 64 + 2 * c2], ga[gi * 64 + 2 * c2 + 1]);
        }
    } else {
        __shared__ int nz;
        if (tid == 0) nz = 0;
        __syncthreads();
        int w = ei_words[2 * tid * 2500 + 1];
        if (w != 0) atomicAdd(&nz, 1);
        __syncthreads();
        if (tid == 0) g_is64 = (nz == 0) ? 1 : 0;
    }
}

// ---------- fused edge MLP: 512 thr, 4m x 4n, double-buffered X, gmem B frags ----------
__global__ __launch_bounds__(NTHREADS, 2)
void edge_mlp_kernel(const float* __restrict__ edge_attr,
                     const float* __restrict__ edge_mask,
                     const void* __restrict__ edge_index,
                     const void* __restrict__ eg_index,
                     const float* __restrict__ b1,
                     const float* __restrict__ b2,
                     float* __restrict__ out) {
    extern __shared__ char smp[];
    __half2* sX[2] = { (__half2*)(smp + SMEM_X0), (__half2*)(smp + SMEM_X1) };
    __half2* sH2 = (__half2*)(smp + SMEM_H);
    int*   sS   = (int*)(smp + OFF_S);
    int*   sR   = (int*)(smp + OFF_R);
    int*   sG   = (int*)(smp + OFF_G);
    float* sMsk = (float*)(smp + OFF_MSK);
    float* sB1  = (float*)(smp + OFF_B1);
    float* sB2  = (float*)(smp + OFF_B2);

    const int tid  = threadIdx.x;
    const int lane = tid & 31;
    const int w    = tid >> 5;           // 0..15
    const int g    = lane >> 2;
    const int t    = lane & 3;
    const int e0   = blockIdx.x * TILE_M;

    const uint2* w1f = (const uint2*)g_w1f;   // [ (s*16+n8)*32 + lane ]
    const uint2* w2f = (const uint2*)g_w2f;   // [ (s*8 +n8)*32 + lane ]

    // indices / mask / biases
    if (tid < 128) {
        if (g_is64) {
            const long long* ei = (const long long*)edge_index;
            const long long* eg = (const long long*)eg_index;
            sS[tid] = (int)ei[e0 + tid];
            sR[tid] = (int)ei[E_TOTAL + e0 + tid];
            sG[tid] = (int)eg[e0 + tid];
        } else {
            const int* ei = (const int*)edge_index;
            const int* eg = (const int*)eg_index;
            sS[tid] = ei[e0 + tid];
            sR[tid] = ei[E_TOTAL + e0 + tid];
            sG[tid] = eg[e0 + tid];
        }
        sMsk[tid] = edge_mask[e0 + tid];
        sB1[tid]  = b1[tid];
        if (tid < 64) sB2[tid] = b2[tid];
    }
    __syncthreads();

    // ---- stage helper: fills sX[buf] with segment seg ----
    // seg0: half0 = edge_attr (cvt f32->f16), half1 = senders
    // seg1: half0 = receivers,               half1 = globals
    // All gather/stream loads use L1::no_allocate to keep weight tables L1-resident.
    #define STAGE_X(SEG, BUF) do {                                              \
        _Pragma("unroll")                                                       \
        for (int i = 0; i < 4; i++) {                                           \
            int f = i * NTHREADS + tid, r = f >> 4, q = f & 15;                 \
            uint2 u;                                                            \
            if ((SEG) == 0) {                                                   \
                float4 v = ldg_na_f4(edge_attr + (size_t)(e0 + r) * 64 + q * 4);\
                u.x = h2u(__floats2half2_rn(v.x, v.y));                         \
                u.y = h2u(__floats2half2_rn(v.z, v.w));                         \
            } else {                                                            \
                u = ldg_na_u2(g_mn2 + (size_t)sR[r] * 32 + q * 2);              \
            }                                                                   \
            *(uint2*)(sX[BUF] + r * LDA + q * 2) = u;                           \
        }                                                                       \
        _Pragma("unroll")                                                       \
        for (int i = 0; i < 4; i++) {                                           \
            int f = i * NTHREADS + tid, r = f >> 4, q = f & 15;                 \
            uint2 u;                                                            \
            if ((SEG) == 0) u = ldg_na_u2(g_mn2 + (size_t)sS[r] * 32 + q * 2);  \
            else            u = ldg_na_u2(g_ga2 + (size_t)sG[r] * 32 + q * 2);  \
            *(uint2*)(sX[BUF] + r * LDA + 32 + q * 2) = u;                      \
        }                                                                       \
    } while (0)

    // ---------------- GEMM1: H[128][128] = X[128][256] @ W1 -------------
    // 16 warps as 4(m) x 4(n); warp tile 32 x 32
    const int m0 = (w & 3) * 32;
    const int wn = w >> 2;               // 0..3, n-block of 32
    float acc[2][4][4];
    #pragma unroll
    for (int mi = 0; mi < 2; mi++)
        #pragma unroll
        for (int ni = 0; ni < 4; ni++)
            #pragma unroll
            for (int j = 0; j < 4; j++) acc[mi][ni][j] = 0.0f;

    STAGE_X(0, 0);
    __syncthreads();
    STAGE_X(1, 1);          // overlaps with seg0 compute below (per-warp scoreboard)

    #pragma unroll
    for (int seg = 0; seg < 2; seg++) {
        const __half2* sXb = sX[seg];
        #pragma unroll
        for (int k16 = 0; k16 < 8; k16++) {
            const int s   = seg * 8 + k16;
            const int kk2 = k16 * 8;
            uint32_t a[2][4];
            #pragma unroll
            for (int mi = 0; mi < 2; mi++) {
                const uint32_t* A0 = (const uint32_t*)(sXb + (m0 + mi * 16 + g) * LDA + kk2 + t);
                const uint32_t* A1 = (const uint32_t*)(sXb + (m0 + mi * 16 + g + 8) * LDA + kk2 + t);
                a[mi][0] = A0[0]; a[mi][1] = A1[0];
                a[mi][2] = A0[4]; a[mi][3] = A1[4];
            }
            #pragma unroll
            for (int ni = 0; ni < 4; ni++) {
                int n8 = wn * 4 + ni;
                uint2 bu = w1f[(s * 16 + n8) * 32 + lane];
                uint32_t b[2] = { bu.x, bu.y };
                mma_f16(acc[0][ni], a[0], b);
                mma_f16(acc[1][ni], a[1], b);
            }
        }
        if (seg == 0) __syncthreads();   // buf1 fully staged before seg1 reads
    }
    __syncthreads();   // all buf reads done before H (aliases buf0) overwrite

    // ---- epilogue 1: bias + ReLU -> half2 -> sH ----
    #pragma unroll
    for (int mi = 0; mi < 2; mi++) {
        #pragma unroll
        for (int ni = 0; ni < 4; ni++) {
            int row0 = m0 + mi * 16 + g;
            int row1 = row0 + 8;
            int col  = wn * 32 + ni * 8 + 2 * t;
            float bb0 = sB1[col], bb1 = sB1[col + 1];
            float h00 = fmaxf(acc[mi][ni][0] + bb0, 0.0f);
            float h01 = fmaxf(acc[mi][ni][1] + bb1, 0.0f);
            float h10 = fmaxf(acc[mi][ni][2] + bb0, 0.0f);
            float h11 = fmaxf(acc[mi][ni][3] + bb1, 0.0f);
            sH2[row0 * LDA + (col >> 1)] = __floats2half2_rn(h00, h01);
            sH2[row1 * LDA + (col >> 1)] = __floats2half2_rn(h10, h11);
        }
    }
    __syncthreads();

    // ---------------- GEMM2: OUT[128][64] = H[128][128] @ W2 ------------
    // 16 warps as 4(m) x 4(n); warp tile 32 x 16
    const int m2 = m0;
    const int n2 = wn * 16;
    float acc2[2][2][4];
    #pragma unroll
    for (int mi = 0; mi < 2; mi++)
        #pragma unroll
        for (int ni = 0; ni < 2; ni++)
            #pragma unroll
            for (int j = 0; j < 4; j++) acc2[mi][ni][j] = 0.0f;

    #pragma unroll
    for (int s = 0; s < 8; s++) {
        const int kk2 = s * 8;
        uint32_t a[2][4];
        #pragma unroll
        for (int mi = 0; mi < 2; mi++) {
            const uint32_t* A0 = (const uint32_t*)(sH2 + (m2 + mi * 16 + g) * LDA + kk2 + t);
            const uint32_t* A1 = (const uint32_t*)(sH2 + (m2 + mi * 16 + g + 8) * LDA + kk2 + t);
            a[mi][0] = A0[0]; a[mi][1] = A1[0];
            a[mi][2] = A0[4]; a[mi][3] = A1[4];
        }
        #pragma unroll
        for (int ni = 0; ni < 2; ni++) {
            int n8 = wn * 2 + ni;
            uint2 bu = w2f[(s * 8 + n8) * 32 + lane];
            uint32_t b[2] = { bu.x, bu.y };
            mma_f16(acc2[0][ni], a[0], b);
            mma_f16(acc2[1][ni], a[1], b);
        }
    }

    // ---- epilogue 2: mask * (acc + b2), direct float2 stores ----
    #pragma unroll
    for (int mi = 0; mi < 2; mi++) {
        int row0 = m2 + mi * 16 + g;
        int row1 = row0 + 8;
        float mk0 = sMsk[row0];
        float mk1 = sMsk[row1];
        #pragma unroll
        for (int ni = 0; ni < 2; ni++) {
            int col = n2 + ni * 8 + 2 * t;
            float bb0 = sB2[col], bb1 = sB2[col + 1];
            float2 v0 = make_float2(mk0 * (acc2[mi][ni][0] + bb0),
                                    mk0 * (acc2[mi][ni][1] + bb1));
            float2 v1 = make_float2(mk1 * (acc2[mi][ni][2] + bb0),
                                    mk1 * (acc2[mi][ni][3] + bb1));
            *(float2*)(out + (size_t)(e0 + row0) * 64 + col) = v0;
            *(float2*)(out + (size_t)(e0 + row1) * 64 + col) = v1;
        }
    }
    #undef STAGE_X
}

extern "C" void kernel_launch(void* const* d_in, const int* in_sizes, int n_in,
                              void* d_out, int out_size) {
    const float* node_attr   = (const float*)d_in[0];
    const float* edge_attr   = (const float*)d_in[1];
    const float* global_attr = (const float*)d_in[2];
    const float* node_mask   = (const float*)d_in[3];
    const float* edge_mask   = (const float*)d_in[4];
    const void*  edge_index  = d_in[5];
    const void*  eg_index    = d_in[6];
    const float* W1          = (const float*)d_in[7];
    const float* b1          = (const float*)d_in[8];
    const float* W2          = (const float*)d_in[9];
    const float* b2          = (const float*)d_in[10];
    float*       out         = (float*)d_out;

    cudaFuncSetAttribute(edge_mlp_kernel,
                         cudaFuncAttributeMaxDynamicSharedMemorySize, SMEM_BYTES);

    prep_all<<<PREP_BLOCKS, 256>>>(node_attr, node_mask, W1, W2, global_attr,
                                   (const int*)edge_index);
    edge_mlp_kernel<<<E_TOTAL / TILE_M, NTHREADS, SMEM_BYTES>>>(
        edge_attr, edge_mask, edge_index, eg_index, b1, b2, out);
}

// round 16
// speedup vs baseline: 1.1690x; 1.1690x over previous
#include <cuda_runtime.h>
#include <cuda_fp16.h>
#include <cstdint>

// Problem constants
#define E_TOTAL   640000
#define N_NODES   20000
#define N_GRAPHS  16
#define TILE_M    128
#define NTHREADS  512

#define LDA  68   // X buf / H rows [128][64 h2], padded (h2 units)

// smem byte offsets: two X buffers; H aliases buf0
#define SMEM_X0   0        // 128*68*4 = 34816
#define SMEM_X1   34816    // -> 69632
#define SMEM_H    0
#define OFF_S     69632
#define OFF_R     70144
#define OFF_G     70656
#define OFF_MSK   71168
#define OFF_B1    71680
#define OFF_B2    72192
#define SMEM_BYTES 72448

// ---------- scratch ----------
__device__ __half2 g_mn2[N_NODES * 32];    // masked nodes [node][32 h2]
__device__ __half2 g_ga2[N_GRAPHS * 32];   // global_attr fp16 [g][32 h2]
// paired fragment-linear weights: one uint4 per lane covers TWO n8 tiles
// w1q: [s(16)][np(8)][lane(32)] uint4 ; w2q: [s(8)][np(4)][lane(32)] uint4
__device__ uint4 g_w1q[16 * 8 * 32];       // 64KB
__device__ uint4 g_w2q[8 * 4 * 32];        // 16KB
__device__ int   g_is64;

__device__ __forceinline__ void mma_f16(float c[4], const uint32_t a[4], const uint32_t b[2]) {
    asm volatile(
        "mma.sync.aligned.m16n8k16.row.col.f32.f16.f16.f32 "
        "{%0,%1,%2,%3}, {%4,%5,%6,%7}, {%8,%9}, {%0,%1,%2,%3};"
        : "+f"(c[0]), "+f"(c[1]), "+f"(c[2]), "+f"(c[3])
        : "r"(a[0]), "r"(a[1]), "r"(a[2]), "r"(a[3]), "r"(b[0]), "r"(b[1]));
}
__device__ __forceinline__ uint32_t h2u(__half2 h) { return *(uint32_t*)&h; }
__device__ __forceinline__ uint32_t smem_u32(const void* p) {
    uint32_t a;
    asm("{ .reg .u64 t; cvta.to.shared.u64 t, %1; cvt.u32.u64 %0, t; }" : "=r"(a) : "l"(p));
    return a;
}
// ldmatrix x4: loads the full m16k16 A fragment (4 regs) in one instruction
__device__ __forceinline__ void ldsm_x4(uint32_t r[4], uint32_t saddr) {
    asm volatile("ldmatrix.sync.aligned.m8n8.x4.shared.b16 {%0,%1,%2,%3}, [%4];"
                 : "=r"(r[0]), "=r"(r[1]), "=r"(r[2]), "=r"(r[3]) : "r"(saddr));
}

// half2 from W1[k][n] (W1 row-major [256][128])
__device__ __forceinline__ __half2 w1h2(const float* W1, int k2, int n) {
    return __floats2half2_rn(W1[(2 * k2) * 128 + n], W1[(2 * k2 + 1) * 128 + n]);
}
__device__ __forceinline__ __half2 w2h2(const float* W2, int k2, int n) {
    return __floats2half2_rn(W2[(2 * k2) * 64 + n], W2[(2 * k2 + 1) * 64 + n]);
}

// ---------- single prep kernel ----------
// blocks [0,2500): masked nodes; [2500,2516): W1 paired-frag; [2516,2520): W2
// paired-frag; [2520,2522): global_attr fp16; 2522: index dtype detect.
#define PREP_BLOCKS 2523
__global__ void prep_all(const float* __restrict__ na, const float* __restrict__ nm,
                         const float* __restrict__ W1, const float* __restrict__ W2,
                         const float* __restrict__ ga, const int* __restrict__ ei_words) {
    int bid = blockIdx.x, tid = threadIdx.x;
    if (bid < 2500) {
        int i = bid * 256 + tid;
        if (i < N_NODES * 32) {
            int node = i >> 5, c2 = i & 31;
            float m = nm[node];
            const float* s = na + (size_t)node * 64 + c2 * 2;
            g_mn2[i] = __floats2half2_rn(s[0] * m, s[1] * m);
        }
    } else if (bid < 2516) {
        // one uint4 per thread: j = (s*8+np)*32 + lane
        int j = (bid - 2500) * 256 + tid;       // < 4096
        int s    = j >> 8;
        int np   = (j >> 5) & 7;
        int lane = j & 31;
        int g = lane >> 2, t = lane & 3;
        int na_ = np * 16 + g;          // n8 even tile
        int nb_ = np * 16 + 8 + g;      // n8 odd tile
        int k2a = s * 8 + t, k2b = s * 8 + t + 4;
        uint4 u;
        u.x = h2u(w1h2(W1, k2a, na_)); u.y = h2u(w1h2(W1, k2b, na_));
        u.z = h2u(w1h2(W1, k2a, nb_)); u.w = h2u(w1h2(W1, k2b, nb_));
        g_w1q[j] = u;
    } else if (bid < 2520) {
        int j = (bid - 2516) * 256 + tid;       // < 1024
        int s    = j >> 7;
        int np   = (j >> 5) & 3;
        int lane = j & 31;
        int g = lane >> 2, t = lane & 3;
        int na_ = np * 16 + g;
        int nb_ = np * 16 + 8 + g;
        int k2a = s * 8 + t, k2b = s * 8 + t + 4;
        uint4 u;
        u.x = h2u(w2h2(W2, k2a, na_)); u.y = h2u(w2h2(W2, k2b, na_));
        u.z = h2u(w2h2(W2, k2a, nb_)); u.w = h2u(w2h2(W2, k2b, nb_));
        g_w2q[j] = u;
    } else if (bid < 2522) {
        int j = (bid - 2520) * 256 + tid;       // < 512
        if (j < N_GRAPHS * 32) {
            int gi = j >> 5, c2 = j & 31;
            g_ga2[j] = __floats2half2_rn(ga[gi * 64 + 2 * c2], ga[gi * 64 + 2 * c2 + 1]);
        }
    } else {
        __shared__ int nz;
        if (tid == 0) nz = 0;
        __syncthreads();
        int w = ei_words[2 * tid * 2500 + 1];
        if (w != 0) atomicAdd(&nz, 1);
        __syncthreads();
        if (tid == 0) g_is64 = (nz == 0) ? 1 : 0;
    }
}

// ---------- fused edge MLP: 512 thr, 4m x 4n, dbl-buffered X, LDSM + LDG.128 frags ----------
__global__ __launch_bounds__(NTHREADS, 2)
void edge_mlp_kernel(const float* __restrict__ edge_attr,
                     const float* __restrict__ edge_mask,
                     const void* __restrict__ edge_index,
                     const void* __restrict__ eg_index,
                     const float* __restrict__ b1,
                     const float* __restrict__ b2,
                     float* __restrict__ out) {
    extern __shared__ char smp[];
    __half2* sX[2] = { (__half2*)(smp + SMEM_X0), (__half2*)(smp + SMEM_X1) };
    __half2* sH2 = (__half2*)(smp + SMEM_H);
    int*   sS   = (int*)(smp + OFF_S);
    int*   sR   = (int*)(smp + OFF_R);
    int*   sG   = (int*)(smp + OFF_G);
    float* sMsk = (float*)(smp + OFF_MSK);
    float* sB1  = (float*)(smp + OFF_B1);
    float* sB2  = (float*)(smp + OFF_B2);

    const int tid  = threadIdx.x;
    const int lane = tid & 31;
    const int w    = tid >> 5;           // 0..15
    const int g    = lane >> 2;
    const int t    = lane & 3;
    const int e0   = blockIdx.x * TILE_M;
    const uint32_t sbase = smem_u32(smp);

    // indices / mask / biases
    if (tid < 128) {
        if (g_is64) {
            const long long* ei = (const long long*)edge_index;
            const long long* eg = (const long long*)eg_index;
            sS[tid] = (int)ei[e0 + tid];
            sR[tid] = (int)ei[E_TOTAL + e0 + tid];
            sG[tid] = (int)eg[e0 + tid];
        } else {
            const int* ei = (const int*)edge_index;
            const int* eg = (const int*)eg_index;
            sS[tid] = ei[e0 + tid];
            sR[tid] = ei[E_TOTAL + e0 + tid];
            sG[tid] = eg[e0 + tid];
        }
        sMsk[tid] = edge_mask[e0 + tid];
        sB1[tid]  = b1[tid];
        if (tid < 64) sB2[tid] = b2[tid];
    }
    __syncthreads();

    // ---- stage helper: fills sX[buf] with segment seg (plain cached loads) ----
    #define STAGE_X(SEG, BUF) do {                                              \
        _Pragma("unroll")                                                       \
        for (int i = 0; i < 4; i++) {                                           \
            int f = i * NTHREADS + tid, r = f >> 4, q = f & 15;                 \
            uint2 u;                                                            \
            if ((SEG) == 0) {                                                   \
                float4 v = *(const float4*)(edge_attr + (size_t)(e0 + r) * 64 + q * 4); \
                u.x = h2u(__floats2half2_rn(v.x, v.y));                         \
                u.y = h2u(__floats2half2_rn(v.z, v.w));                         \
            } else {                                                            \
                u = *(const uint2*)(g_mn2 + (size_t)sR[r] * 32 + q * 2);        \
            }                                                                   \
            *(uint2*)(sX[BUF] + r * LDA + q * 2) = u;                           \
        }                                                                       \
        _Pragma("unroll")                                                       \
        for (int i = 0; i < 4; i++) {                                           \
            int f = i * NTHREADS + tid, r = f >> 4, q = f & 15;                 \
            uint2 u;                                                            \
            if ((SEG) == 0) u = *(const uint2*)(g_mn2 + (size_t)sS[r] * 32 + q * 2); \
            else            u = *(const uint2*)(g_ga2 + (size_t)sG[r] * 32 + q * 2); \
            *(uint2*)(sX[BUF] + r * LDA + 32 + q * 2) = u;                      \
        }                                                                       \
    } while (0)

    // ---------------- GEMM1: H[128][128] = X[128][256] @ W1 -------------
    // 16 warps as 4(m) x 4(n); warp tile 32 x 32
    const int m0 = (w & 3) * 32;
    const int wn = w >> 2;               // 0..3, n-block of 32
    // ldmatrix per-lane address component: lanes 0-15 -> rows, 16-31 -> k+8 halves
    const int lrow = lane & 15, kh = lane >> 4;
    const uint32_t aoff = (uint32_t)(((m0 + lrow) * LDA + kh * 4) * 4);

    float acc[2][4][4];
    #pragma unroll
    for (int mi = 0; mi < 2; mi++)
        #pragma unroll
        for (int ni = 0; ni < 4; ni++)
            #pragma unroll
            for (int j = 0; j < 4; j++) acc[mi][ni][j] = 0.0f;

    STAGE_X(0, 0);
    __syncthreads();
    STAGE_X(1, 1);          // overlaps with seg0 compute (per-warp scoreboard)

    #pragma unroll
    for (int seg = 0; seg < 2; seg++) {
        const uint32_t abase = sbase + (seg ? SMEM_X1 : SMEM_X0) + aoff;
        #pragma unroll
        for (int k16 = 0; k16 < 8; k16++) {
            const int s = seg * 8 + k16;
            uint32_t a[2][4];
            ldsm_x4(a[0], abase + k16 * 32);
            ldsm_x4(a[1], abase + 16 * LDA * 4 + k16 * 32);
            #pragma unroll
            for (int jj = 0; jj < 2; jj++) {
                uint4 bu = g_w1q[(s * 8 + wn * 2 + jj) * 32 + lane];
                uint32_t bA[2] = { bu.x, bu.y };
                uint32_t bB[2] = { bu.z, bu.w };
                mma_f16(acc[0][jj * 2],     a[0], bA);
                mma_f16(acc[1][jj * 2],     a[1], bA);
                mma_f16(acc[0][jj * 2 + 1], a[0], bB);
                mma_f16(acc[1][jj * 2 + 1], a[1], bB);
            }
        }
        if (seg == 0) __syncthreads();   // buf1 fully staged before seg1 reads
    }
    __syncthreads();   // all buf reads done before H (aliases buf0) overwrite

    // ---- epilogue 1: bias + ReLU -> half2 -> sH ----
    #pragma unroll
    for (int mi = 0; mi < 2; mi++) {
        #pragma unroll
        for (int ni = 0; ni < 4; ni++) {
            int row0 = m0 + mi * 16 + g;
            int row1 = row0 + 8;
            int col  = wn * 32 + ni * 8 + 2 * t;
            float bb0 = sB1[col], bb1 = sB1[col + 1];
            float h00 = fmaxf(acc[mi][ni][0] + bb0, 0.0f);
            float h01 = fmaxf(acc[mi][ni][1] + bb1, 0.0f);
            float h10 = fmaxf(acc[mi][ni][2] + bb0, 0.0f);
            float h11 = fmaxf(acc[mi][ni][3] + bb1, 0.0f);
            sH2[row0 * LDA + (col >> 1)] = __floats2half2_rn(h00, h01);
            sH2[row1 * LDA + (col >> 1)] = __floats2half2_rn(h10, h11);
        }
    }
    __syncthreads();

    // ---------------- GEMM2: OUT[128][64] = H[128][128] @ W2 ------------
    // 16 warps as 4(m) x 4(n); warp tile 32 x 16
    const int m2 = m0;
    const int n2 = wn * 16;
    const uint32_t hbase = sbase + SMEM_H + aoff;   // same row/k mapping as GEMM1
    float acc2[2][2][4];
    #pragma unroll
    for (int mi = 0; mi < 2; mi++)
        #pragma unroll
        for (int ni = 0; ni < 2; ni++)
            #pragma unroll
            for (int j = 0; j < 4; j++) acc2[mi][ni][j] = 0.0f;

    #pragma unroll
    for (int s = 0; s < 8; s++) {
        uint32_t a[2][4];
        ldsm_x4(a[0], hbase + s * 32);
        ldsm_x4(a[1], hbase + 16 * LDA * 4 + s * 32);
        uint4 bu = g_w2q[(s * 4 + wn) * 32 + lane];
        uint32_t bA[2] = { bu.x, bu.y };
        uint32_t bB[2] = { bu.z, bu.w };
        mma_f16(acc2[0][0], a[0], bA);
        mma_f16(acc2[1][0], a[1], bA);
        mma_f16(acc2[0][1], a[0], bB);
        mma_f16(acc2[1][1], a[1], bB);
    }

    // ---- epilogue 2: mask * (acc + b2), direct float2 stores ----
    #pragma unroll
    for (int mi = 0; mi < 2; mi++) {
        int row0 = m2 + mi * 16 + g;
        int row1 = row0 + 8;
        float mk0 = sMsk[row0];
        float mk1 = sMsk[row1];
        #pragma unroll
        for (int ni = 0; ni < 2; ni++) {
            int col = n2 + ni * 8 + 2 * t;
            float bb0 = sB2[col], bb1 = sB2[col + 1];
            float2 v0 = make_float2(mk0 * (acc2[mi][ni][0] + bb0),
                                    mk0 * (acc2[mi][ni][1] + bb1));
            float2 v1 = make_float2(mk1 * (acc2[mi][ni][2] + bb0),
                                    mk1 * (acc2[mi][ni][3] + bb1));
            *(float2*)(out + (size_t)(e0 + row0) * 64 + col) = v0;
            *(float2*)(out + (size_t)(e0 + row1) * 64 + col) = v1;
        }
    }
    #undef STAGE_X
}

extern "C" void kernel_launch(void* const* d_in, const int* in_sizes, int n_in,
                              void* d_out, int out_size) {
    const float* node_attr   = (const float*)d_in[0];
    const float* edge_attr   = (const float*)d_in[1];
    const float* global_attr = (const float*)d_in[2];
    const float* node_mask   = (const float*)d_in[3];
    const float* edge_mask   = (const float*)d_in[4];
    const void*  edge_index  = d_in[5];
    const void*  eg_index    = d_in[6];
    const float* W1          = (const float*)d_in[7];
    const float* b1          = (const float*)d_in[8];
    const float* W2          = (const float*)d_in[9];
    const float* b2          = (const float*)d_in[10];
    float*       out         = (float*)d_out;

    cudaFuncSetAttribute(edge_mlp_kernel,
                         cudaFuncAttributeMaxDynamicSharedMemorySize, SMEM_BYTES);

    prep_all<<<PREP_BLOCKS, 256>>>(node_attr, node_mask, W1, W2, global_attr,
                                   (const int*)edge_index);
    edge_mlp_kernel<<<E_TOTAL / TILE_M, NTHREADS, SMEM_BYTES>>>(
        edge_attr, edge_mask, edge_index, eg_index, b1, b2, out);
}

// round 17
// speedup vs baseline: 1.2208x; 1.0443x over previous
#include <cuda_runtime.h>
#include <cuda_fp16.h>
#include <cstdint>

// Problem constants
#define E_TOTAL   640000
#define N_NODES   20000
#define N_GRAPHS  16
#define TILE_M    128
#define NTHREADS  512

#define LDA  68   // X buf / H rows [128][64 h2], padded (h2 units)

// smem byte offsets: two X buffers; H aliases buf0
#define SMEM_X0   0        // 128*68*4 = 34816
#define SMEM_X1   34816    // -> 69632
#define SMEM_H    0
#define OFF_S     69632
#define OFF_R     70144
#define OFF_G     70656
#define OFF_MSK   71168
#define OFF_B1    71680
#define OFF_B2    72192
#define SMEM_BYTES 72448

// ---------- scratch ----------
__device__ __half2 g_mn2[N_NODES * 32];    // masked nodes [node][32 h2]
__device__ __half2 g_ga2[N_GRAPHS * 32];   // global_attr fp16 [g][32 h2]
// paired fragment-linear weights: one uint4 per lane covers TWO n8 tiles
// w1q: [s(16)][np(8)][lane(32)] uint4 ; w2q: [s(8)][np(4)][lane(32)] uint4
__device__ uint4 g_w1q[16 * 8 * 32];       // 64KB
__device__ uint4 g_w2q[8 * 4 * 32];        // 16KB
__device__ int   g_is64;

__device__ __forceinline__ void mma_f16(float c[4], const uint32_t a[4], const uint32_t b[2]) {
    asm volatile(
        "mma.sync.aligned.m16n8k16.row.col.f32.f16.f16.f32 "
        "{%0,%1,%2,%3}, {%4,%5,%6,%7}, {%8,%9}, {%0,%1,%2,%3};"
        : "+f"(c[0]), "+f"(c[1]), "+f"(c[2]), "+f"(c[3])
        : "r"(a[0]), "r"(a[1]), "r"(a[2]), "r"(a[3]), "r"(b[0]), "r"(b[1]));
}
__device__ __forceinline__ uint32_t h2u(__half2 h) { return *(uint32_t*)&h; }
__device__ __forceinline__ uint32_t smem_u32(const void* p) {
    uint32_t a;
    asm("{ .reg .u64 t; cvta.to.shared.u64 t, %1; cvt.u32.u64 %0, t; }" : "=r"(a) : "l"(p));
    return a;
}
// ldmatrix x4: loads the full m16k16 A fragment (4 regs) in one instruction
__device__ __forceinline__ void ldsm_x4(uint32_t r[4], uint32_t saddr) {
    asm volatile("ldmatrix.sync.aligned.m8n8.x4.shared.b16 {%0,%1,%2,%3}, [%4];"
                 : "=r"(r[0]), "=r"(r[1]), "=r"(r[2]), "=r"(r[3]) : "r"(saddr));
}

// half2 from W1[k][n] (W1 row-major [256][128])
__device__ __forceinline__ __half2 w1h2(const float* W1, int k2, int n) {
    return __floats2half2_rn(W1[(2 * k2) * 128 + n], W1[(2 * k2 + 1) * 128 + n]);
}
__device__ __forceinline__ __half2 w2h2(const float* W2, int k2, int n) {
    return __floats2half2_rn(W2[(2 * k2) * 64 + n], W2[(2 * k2 + 1) * 64 + n]);
}

// ---------- single prep kernel ----------
// blocks [0,2500): masked nodes; [2500,2516): W1 paired-frag; [2516,2520): W2
// paired-frag; [2520,2522): global_attr fp16; 2522: index dtype detect.
#define PREP_BLOCKS 2523
__global__ void prep_all(const float* __restrict__ na, const float* __restrict__ nm,
                         const float* __restrict__ W1, const float* __restrict__ W2,
                         const float* __restrict__ ga, const int* __restrict__ ei_words) {
    int bid = blockIdx.x, tid = threadIdx.x;
    if (bid < 2500) {
        int i = bid * 256 + tid;
        if (i < N_NODES * 32) {
            int node = i >> 5, c2 = i & 31;
            float m = nm[node];
            const float* s = na + (size_t)node * 64 + c2 * 2;
            g_mn2[i] = __floats2half2_rn(s[0] * m, s[1] * m);
        }
    } else if (bid < 2516) {
        // one uint4 per thread: j = (s*8+np)*32 + lane
        int j = (bid - 2500) * 256 + tid;       // < 4096
        int s    = j >> 8;
        int np   = (j >> 5) & 7;
        int lane = j & 31;
        int g = lane >> 2, t = lane & 3;
        int na_ = np * 16 + g;          // n8 even tile
        int nb_ = np * 16 + 8 + g;      // n8 odd tile
        int k2a = s * 8 + t, k2b = s * 8 + t + 4;
        uint4 u;
        u.x = h2u(w1h2(W1, k2a, na_)); u.y = h2u(w1h2(W1, k2b, na_));
        u.z = h2u(w1h2(W1, k2a, nb_)); u.w = h2u(w1h2(W1, k2b, nb_));
        g_w1q[j] = u;
    } else if (bid < 2520) {
        int j = (bid - 2516) * 256 + tid;       // < 1024
        int s    = j >> 7;
        int np   = (j >> 5) & 3;
        int lane = j & 31;
        int g = lane >> 2, t = lane & 3;
        int na_ = np * 16 + g;
        int nb_ = np * 16 + 8 + g;
        int k2a = s * 8 + t, k2b = s * 8 + t + 4;
        uint4 u;
        u.x = h2u(w2h2(W2, k2a, na_)); u.y = h2u(w2h2(W2, k2b, na_));
        u.z = h2u(w2h2(W2, k2a, nb_)); u.w = h2u(w2h2(W2, k2b, nb_));
        g_w2q[j] = u;
    } else if (bid < 2522) {
        int j = (bid - 2520) * 256 + tid;       // < 512
        if (j < N_GRAPHS * 32) {
            int gi = j >> 5, c2 = j & 31;
            g_ga2[j] = __floats2half2_rn(ga[gi * 64 + 2 * c2], ga[gi * 64 + 2 * c2 + 1]);
        }
    } else {
        __shared__ int nz;
        if (tid == 0) nz = 0;
        __syncthreads();
        int w = ei_words[2 * tid * 2500 + 1];
        if (w != 0) atomicAdd(&nz, 1);
        __syncthreads();
        if (tid == 0) g_is64 = (nz == 0) ? 1 : 0;
    }
}

// ---------- fused edge MLP: 512 thr, 4m x 4n, LDSM + pipelined LDG.128 B frags ----------
__global__ __launch_bounds__(NTHREADS, 2)
void edge_mlp_kernel(const float* __restrict__ edge_attr,
                     const float* __restrict__ edge_mask,
                     const void* __restrict__ edge_index,
                     const void* __restrict__ eg_index,
                     const float* __restrict__ b1,
                     const float* __restrict__ b2,
                     float* __restrict__ out) {
    extern __shared__ char smp[];
    __half2* sX[2] = { (__half2*)(smp + SMEM_X0), (__half2*)(smp + SMEM_X1) };
    __half2* sH2 = (__half2*)(smp + SMEM_H);
    int*   sS   = (int*)(smp + OFF_S);
    int*   sR   = (int*)(smp + OFF_R);
    int*   sG   = (int*)(smp + OFF_G);
    float* sMsk = (float*)(smp + OFF_MSK);
    float* sB1  = (float*)(smp + OFF_B1);
    float* sB2  = (float*)(smp + OFF_B2);

    const int tid  = threadIdx.x;
    const int lane = tid & 31;
    const int w    = tid >> 5;           // 0..15
    const int g    = lane >> 2;
    const int t    = lane & 3;
    const int e0   = blockIdx.x * TILE_M;
    const uint32_t sbase = smem_u32(smp);

    // indices / mask / biases
    if (tid < 128) {
        if (g_is64) {
            const long long* ei = (const long long*)edge_index;
            const long long* eg = (const long long*)eg_index;
            sS[tid] = (int)ei[e0 + tid];
            sR[tid] = (int)ei[E_TOTAL + e0 + tid];
            sG[tid] = (int)eg[e0 + tid];
        } else {
            const int* ei = (const int*)edge_index;
            const int* eg = (const int*)eg_index;
            sS[tid] = ei[e0 + tid];
            sR[tid] = ei[E_TOTAL + e0 + tid];
            sG[tid] = eg[e0 + tid];
        }
        sMsk[tid] = edge_mask[e0 + tid];
        sB1[tid]  = b1[tid];
        if (tid < 64) sB2[tid] = b2[tid];
    }
    __syncthreads();

    // ---- stage helper: fills sX[buf] with segment seg ----
    #define STAGE_X(SEG, BUF) do {                                              \
        _Pragma("unroll")                                                       \
        for (int i = 0; i < 4; i++) {                                           \
            int f = i * NTHREADS + tid, r = f >> 4, q = f & 15;                 \
            uint2 u;                                                            \
            if ((SEG) == 0) {                                                   \
                float4 v = *(const float4*)(edge_attr + (size_t)(e0 + r) * 64 + q * 4); \
                u.x = h2u(__floats2half2_rn(v.x, v.y));                         \
                u.y = h2u(__floats2half2_rn(v.z, v.w));                         \
            } else {                                                            \
                u = *(const uint2*)(g_mn2 + (size_t)sR[r] * 32 + q * 2);        \
            }                                                                   \
            *(uint2*)(sX[BUF] + r * LDA + q * 2) = u;                           \
        }                                                                       \
        _Pragma("unroll")                                                       \
        for (int i = 0; i < 4; i++) {                                           \
            int f = i * NTHREADS + tid, r = f >> 4, q = f & 15;                 \
            uint2 u;                                                            \
            if ((SEG) == 0) u = *(const uint2*)(g_mn2 + (size_t)sS[r] * 32 + q * 2); \
            else            u = *(const uint2*)(g_ga2 + (size_t)sG[r] * 32 + q * 2); \
            *(uint2*)(sX[BUF] + r * LDA + 32 + q * 2) = u;                      \
        }                                                                       \
    } while (0)

    // ---------------- GEMM1: H[128][128] = X[128][256] @ W1 -------------
    // 16 warps as 4(m) x 4(n); warp tile 32 x 32
    const int m0 = (w & 3) * 32;
    const int wn = w >> 2;               // 0..3, n-block of 32
    const int lrow = lane & 15, kh = lane >> 4;
    const uint32_t aoff = (uint32_t)(((m0 + lrow) * LDA + kh * 4) * 4);
    // strength-reduced weight pointers (per warp n-column, per lane)
    const uint4* w1p = g_w1q + (wn * 2) * 32 + lane;   // [s*256], pair at +32
    const uint4* w2p = g_w2q + wn * 32 + lane;         // [s*128]

    float acc[2][4][4];
    #pragma unroll
    for (int mi = 0; mi < 2; mi++)
        #pragma unroll
        for (int ni = 0; ni < 4; ni++)
            #pragma unroll
            for (int j = 0; j < 4; j++) acc[mi][ni][j] = 0.0f;

    STAGE_X(0, 0);
    __syncthreads();
    STAGE_X(1, 1);          // overlaps seg0 compute (per-warp scoreboard)

    // B double-buffer: prefetch s=0 pair
    uint4 bu0 = w1p[0];
    uint4 bu1 = w1p[32];

    #pragma unroll
    for (int s = 0; s < 16; s++) {
        if (s == 8) __syncthreads();     // X1 fully staged; all X0 reads done
        const uint32_t abase = sbase + (s < 8 ? SMEM_X0 : SMEM_X1) + aoff;
        uint32_t a[2][4];
        ldsm_x4(a[0], abase + (s & 7) * 32);
        ldsm_x4(a[1], abase + 16 * LDA * 4 + (s & 7) * 32);
        uint4 nb0, nb1;
        if (s < 15) { nb0 = w1p[(s + 1) * 256]; nb1 = w1p[(s + 1) * 256 + 32]; }
        {
            uint32_t bA[2] = { bu0.x, bu0.y };
            uint32_t bB[2] = { bu0.z, bu0.w };
            mma_f16(acc[0][0], a[0], bA);
            mma_f16(acc[1][0], a[1], bA);
            mma_f16(acc[0][1], a[0], bB);
            mma_f16(acc[1][1], a[1], bB);
        }
        {
            uint32_t bA[2] = { bu1.x, bu1.y };
            uint32_t bB[2] = { bu1.z, bu1.w };
            mma_f16(acc[0][2], a[0], bA);
            mma_f16(acc[1][2], a[1], bA);
            mma_f16(acc[0][3], a[0], bB);
            mma_f16(acc[1][3], a[1], bB);
        }
        if (s < 15) { bu0 = nb0; bu1 = nb1; }
    }
    // NOTE: no barrier here. The s==8 barrier proved all X0 (seg0) reads done;
    // remaining warps only read X1, so overwriting H (aliases X0) is safe.

    // ---- epilogue 1: bias + ReLU -> half2 -> sH ----
    #pragma unroll
    for (int mi = 0; mi < 2; mi++) {
        #pragma unroll
        for (int ni = 0; ni < 4; ni++) {
            int row0 = m0 + mi * 16 + g;
            int row1 = row0 + 8;
            int col  = wn * 32 + ni * 8 + 2 * t;
            float bb0 = sB1[col], bb1 = sB1[col + 1];
            float h00 = fmaxf(acc[mi][ni][0] + bb0, 0.0f);
            float h01 = fmaxf(acc[mi][ni][1] + bb1, 0.0f);
            float h10 = fmaxf(acc[mi][ni][2] + bb0, 0.0f);
            float h11 = fmaxf(acc[mi][ni][3] + bb1, 0.0f);
            sH2[row0 * LDA + (col >> 1)] = __floats2half2_rn(h00, h01);
            sH2[row1 * LDA + (col >> 1)] = __floats2half2_rn(h10, h11);
        }
    }
    __syncthreads();

    // ---------------- GEMM2: OUT[128][64] = H[128][128] @ W2 ------------
    // 16 warps as 4(m) x 4(n); warp tile 32 x 16
    const int m2 = m0;
    const int n2 = wn * 16;
    const uint32_t hbase = sbase + SMEM_H + aoff;
    float acc2[2][2][4];
    #pragma unroll
    for (int mi = 0; mi < 2; mi++)
        #pragma unroll
        for (int ni = 0; ni < 2; ni++)
            #pragma unroll
            for (int j = 0; j < 4; j++) acc2[mi][ni][j] = 0.0f;

    uint4 cu = w2p[0];
    #pragma unroll
    for (int s = 0; s < 8; s++) {
        uint32_t a[2][4];
        ldsm_x4(a[0], hbase + s * 32);
        ldsm_x4(a[1], hbase + 16 * LDA * 4 + s * 32);
        uint4 nu;
        if (s < 7) nu = w2p[(s + 1) * 128];
        uint32_t bA[2] = { cu.x, cu.y };
        uint32_t bB[2] = { cu.z, cu.w };
        mma_f16(acc2[0][0], a[0], bA);
        mma_f16(acc2[1][0], a[1], bA);
        mma_f16(acc2[0][1], a[0], bB);
        mma_f16(acc2[1][1], a[1], bB);
        if (s < 7) cu = nu;
    }

    // ---- epilogue 2: mask * (acc + b2), direct float2 stores ----
    #pragma unroll
    for (int mi = 0; mi < 2; mi++) {
        int row0 = m2 + mi * 16 + g;
        int row1 = row0 + 8;
        float mk0 = sMsk[row0];
        float mk1 = sMsk[row1];
        #pragma unroll
        for (int ni = 0; ni < 2; ni++) {
            int col = n2 + ni * 8 + 2 * t;
            float bb0 = sB2[col], bb1 = sB2[col + 1];
            float2 v0 = make_float2(mk0 * (acc2[mi][ni][0] + bb0),
                                    mk0 * (acc2[mi][ni][1] + bb1));
            float2 v1 = make_float2(mk1 * (acc2[mi][ni][2] + bb0),
                                    mk1 * (acc2[mi][ni][3] + bb1));
            *(float2*)(out + (size_t)(e0 + row0) * 64 + col) = v0;
            *(float2*)(out + (size_t)(e0 + row1) * 64 + col) = v1;
        }
    }
    #undef STAGE_X
}

extern "C" void kernel_launch(void* const* d_in, const int* in_sizes, int n_in,
                              void* d_out, int out_size) {
    const float* node_attr   = (const float*)d_in[0];
    const float* edge_attr   = (const float*)d_in[1];
    const float* global_attr = (const float*)d_in[2];
    const float* node_mask   = (const float*)d_in[3];
    const float* edge_mask   = (const float*)d_in[4];
    const void*  edge_index  = d_in[5];
    const void*  eg_index    = d_in[6];
    const float* W1          = (const float*)d_in[7];
    const float* b1          = (const float*)d_in[8];
    const float* W2          = (const float*)d_in[9];
    const float* b2          = (const float*)d_in[10];
    float*       out         = (float*)d_out;

    cudaFuncSetAttribute(edge_mlp_kernel,
                         cudaFuncAttributeMaxDynamicSharedMemorySize, SMEM_BYTES);

    prep_all<<<PREP_BLOCKS, 256>>>(node_attr, node_mask, W1, W2, global_attr,
                                   (const int*)edge_index);
    edge_mlp_kernel<<<E_TOTAL / TILE_M, NTHREADS, SMEM_BYTES>>>(
        edge_attr, edge_mask, edge_index, eg_index, b1, b2, out);
}